// round 14
// baseline (speedup 1.0000x reference)
#include <cuda_runtime.h>
#include <stdint.h>

// B = 1048576, D = 3, L = 16, C = 2, H = 16, S = 1.0
//   res(l) = 16 << l, side = res+1; dense l=0,1,2; hashed l>=3 (hm = 2^19)
//   offsets: 0, 4920, 40864, 315496, then +524288/level (all even)
//   table = concat(ext[524288,2], own[.,2])
//
// R14 = R13 (thread-uniform pairing: x0 even -> all 4 hashed pairs are one
// aligned LDG.128 each; x0 odd -> never paired -> 8x LDG.64; issue measured
// -3.3pts) + __launch_bounds__(256, 8): forces the 32-register budget that
// R13 missed (34 regs -> occ 65.7%; the allocation granularity at 32 regs
// is worth a third of resident warps on this latency-bound kernel).

#define HASH_SPLIT 524288u
#define P2 2654435761u
#define P3 805459861u

__global__ void __launch_bounds__(256, 8)
grid_encode_kernel(const float* __restrict__ pts,
                   const float2* __restrict__ ext,
                   const float2* __restrict__ own,
                   float2* __restrict__ out)
{
    const unsigned gtid = blockIdx.x * 256u + threadIdx.x;
    const unsigned b = gtid >> 4;
    const unsigned l = gtid & 15u;

    const float px_in = __ldg(&pts[3u * b + 0u]);
    const float py_in = __ldg(&pts[3u * b + 1u]);
    const float pz_in = __ldg(&pts[3u * b + 2u]);

    const unsigned res  = 16u << l;
    const float scale   = (float)(res - 1u);
    const unsigned side = res + 1u;

    // pos >= 0.5 always: truncation == floor.
    const float posx = (px_in + 1.0f) * 0.5f * scale + 0.5f;
    const float posy = (py_in + 1.0f) * 0.5f * scale + 0.5f;
    const float posz = (pz_in + 1.0f) * 0.5f * scale + 0.5f;

    const unsigned x0 = (unsigned)posx;
    const unsigned y0 = (unsigned)posy;
    const unsigned z0 = (unsigned)posz;
    const float fx = posx - (float)x0;
    const float fy = posy - (float)y0;
    const float fz = posz - (float)z0;

    const bool hashed = (l >= 3u);
    const unsigned off = hashed ? (315496u + (l - 3u) * 524288u)
                                : (l == 0u ? 0u : (l == 1u ? 4920u : 40864u));

    // ext/own threshold: idx < T -> ext + g ; else own + (g - HASH_SPLIT).
    // l<=2: always ext. l==3: straddles. l>=4: always own.
    const unsigned T = (l < 3u) ? 0xFFFFFFFFu : (l == 3u ? HASH_SPLIT : 0u);
    const float2* __restrict__ ownm = own - HASH_SPLIT;

    const float wx0 = 1.0f - fx, wx1 = fx;
    const float wy[2] = { 1.0f - fy, fy };
    const float wz[2] = { 1.0f - fz, fz };

    float2 v0[4], v1[4];

    if (hashed) {
        // Hash per-axis terms (uint32 wraparound; PRIMES = {1, P2, P3}).
        const unsigned hy0 = y0 * P2;
        const unsigned hz0 = z0 * P3;
        const unsigned hys[2] = { hy0, hy0 + P2 };
        const unsigned hzs[2] = { hz0, hz0 + P3 };

        if ((x0 & 1u) == 0u) {
            // x0 even: every pair occupies one aligned 16B slot {lo, lo+1}.
            // Corner a's slot half = bit0(a). Pairs never cross level/half
            // boundaries (all offsets/sizes even).
#pragma unroll
            for (int p = 0; p < 4; ++p) {
                const int cy = p & 1, cz = (p >> 1) & 1;
                const unsigned hb = hys[cy] ^ hzs[cz];
                const unsigned a  = off + ((x0 ^ hb) & (HASH_SPLIT - 1u));
                const unsigned lo = a & ~1u;
                const float2* q = (lo < T) ? (ext + lo) : (ownm + lo);
                const float4 w4 = __ldg((const float4*)q);
                const bool swap = (a & 1u);
                v0[p] = swap ? make_float2(w4.z, w4.w) : make_float2(w4.x, w4.y);
                v1[p] = swap ? make_float2(w4.x, w4.y) : make_float2(w4.z, w4.w);
            }
        } else {
            // x0 odd: never pairable (x0^(x0+1) >= 3). Two LDG.64 per pair.
#pragma unroll
            for (int p = 0; p < 4; ++p) {
                const int cy = p & 1, cz = (p >> 1) & 1;
                const unsigned hb = hys[cy] ^ hzs[cz];
                const unsigned a  = off + ((x0 ^ hb) & (HASH_SPLIT - 1u));
                const unsigned bb = off + (((x0 + 1u) ^ hb) & (HASH_SPLIT - 1u));
                const float2* qa = (a  < T) ? (ext + a)  : (ownm + a);
                const float2* qb = (bb < T) ? (ext + bb) : (ownm + bb);
                v0[p] = __ldg(qa);
                v1[p] = __ldg(qb);
            }
        }
    } else {
        // Dense levels: all inside ext; corners consecutive (b = a+1);
        // parity alternates with cy/cz (side odd): per-pair branch.
        const unsigned side2 = side * side;
        const unsigned dys[2] = { y0 * side,  y0 * side + side };
        const unsigned dzs[2] = { z0 * side2, z0 * side2 + side2 };
#pragma unroll
        for (int p = 0; p < 4; ++p) {
            const int cy = p & 1, cz = (p >> 1) & 1;
            const unsigned a = off + x0 + dys[cy] + dzs[cz];
            if ((a & 1u) == 0u) {
                const float4 w4 = __ldg((const float4*)(ext + a));
                v0[p] = make_float2(w4.x, w4.y);
                v1[p] = make_float2(w4.z, w4.w);
            } else {
                v0[p] = __ldg(ext + a);
                v1[p] = __ldg(ext + a + 1u);
            }
        }
    }

    float accx = 0.0f, accy = 0.0f;
#pragma unroll
    for (int p = 0; p < 4; ++p) {
        const int cy = p & 1, cz = (p >> 1) & 1;
        const float w = wy[cy] * wz[cz];
        accx += w * (wx0 * v0[p].x + wx1 * v1[p].x);
        accy += w * (wx0 * v0[p].y + wx1 * v1[p].y);
    }

    out[gtid] = make_float2(accx, accy);
}

extern "C" void kernel_launch(void* const* d_in, const int* in_sizes, int n_in,
                              void* d_out, int out_size)
{
    const float*  pts = (const float*)d_in[0];        // [B, 3]
    const float2* ext = (const float2*)d_in[1];       // [524288, 2]
    const float2* own = (const float2*)d_in[2];       // [N_TABLE - 524288, 2]
    float2* out = (float2*)d_out;                     // [B*16] float2

    grid_encode_kernel<<<65536, 256>>>(pts, ext, own, out);
}

// round 15
// speedup vs baseline: 1.0465x; 1.0465x over previous
#include <cuda_runtime.h>
#include <stdint.h>

// B = 1048576, D = 3, L = 16, C = 2, H = 16, S = 1.0
//   res(l) = 16 << l, side = res+1; dense l=0,1,2; hashed l>=3 (hm = 2^19)
//   offsets: 0, 4920, 40864, 315496, then +524288/level (all even)
//   table = concat(ext[524288,2], own[.,2])
//
// FINAL (R15) = R10, the measured champion (289.1us), + truncation floor.
// Structure proven optimal by ablation over R1-R14:
//   - thread = (point, level): coalesced float2 stores, 32 regs, occ ~89%.
//   - loads-only divergent arm split (dense vs hashed); index math and
//     accumulation shared. Tiny per-pair branches keep all 4 pairs' loads
//     interleaved and in flight (beats whole-arm parity branching by 13us).
//   - pair-merge: one aligned LDG.128 when the x-corner pair lands in one
//     16B slot ((a^b)==1; happens for even x0 since PRIMES[0]==1 and for
//     even dense indices), else 2x LDG.64. -25% L2 sectors vs naive.
//   - ext/own select via per-thread threshold T (only l==3 straddles).
//   - all __ldg (measured: .cg harms l1tex on sm_103a); plain stores
//     (stcs neutral); truncation floor (pos >= 0.5 always).

#define HASH_SPLIT 524288u
#define P2 2654435761u
#define P3 805459861u

__global__ void __launch_bounds__(256)
grid_encode_kernel(const float* __restrict__ pts,
                   const float2* __restrict__ ext,
                   const float2* __restrict__ own,
                   float2* __restrict__ out)
{
    const unsigned gtid = blockIdx.x * 256u + threadIdx.x;
    const unsigned b = gtid >> 4;
    const unsigned l = gtid & 15u;

    const float px_in = __ldg(&pts[3u * b + 0u]);
    const float py_in = __ldg(&pts[3u * b + 1u]);
    const float pz_in = __ldg(&pts[3u * b + 2u]);

    const unsigned res  = 16u << l;
    const float scale   = (float)(res - 1u);
    const unsigned side = res + 1u;

    // pos >= 0.5 always (x01 in [0,1], +0.5): truncation == floor.
    const float posx = (px_in + 1.0f) * 0.5f * scale + 0.5f;
    const float posy = (py_in + 1.0f) * 0.5f * scale + 0.5f;
    const float posz = (pz_in + 1.0f) * 0.5f * scale + 0.5f;

    const unsigned x0 = (unsigned)posx;
    const unsigned y0 = (unsigned)posy;
    const unsigned z0 = (unsigned)posz;
    const float fx = posx - (float)x0;
    const float fy = posy - (float)y0;
    const float fz = posz - (float)z0;

    const bool hashed = (l >= 3u);
    const unsigned off = hashed ? (315496u + (l - 3u) * 524288u)
                                : (l == 0u ? 0u : (l == 1u ? 4920u : 40864u));

    // ext/own threshold: idx < T -> ext + g ; else own + (g - HASH_SPLIT).
    // l<=2: always ext. l==3: straddles. l>=4: always own.
    const unsigned T = (l < 3u) ? 0xFFFFFFFFu : (l == 3u ? HASH_SPLIT : 0u);
    const float2* __restrict__ ownm = own - HASH_SPLIT;

    // Hash per-axis terms (uint32 wraparound; PRIMES = {1, P2, P3})
    const unsigned hy0 = y0 * P2;
    const unsigned hz0 = z0 * P3;
    const unsigned hys[2] = { hy0, hy0 + P2 };
    const unsigned hzs[2] = { hz0, hz0 + P3 };

    // Dense per-axis terms (no modulo: side^3 <= hm for l<=2)
    const unsigned side2 = side * side;
    const unsigned dys[2] = { y0 * side,  y0 * side + side };
    const unsigned dzs[2] = { z0 * side2, z0 * side2 + side2 };

    // Global indices for the 4 (y,z) pairs (shared by both load arms).
    unsigned ia[4], ib[4];
#pragma unroll
    for (int p = 0; p < 4; ++p) {
        const int cy = p & 1, cz = (p >> 1) & 1;
        unsigned a, bx;
        if (hashed) {
            const unsigned hb = hys[cy] ^ hzs[cz];
            a  = (x0 ^ hb) & (HASH_SPLIT - 1u);
            bx = ((x0 + 1u) ^ hb) & (HASH_SPLIT - 1u);
        } else {
            const unsigned db = dys[cy] + dzs[cz];
            a  = x0 + db;
            bx = a + 1u;
        }
        ia[p] = off + a;
        ib[p] = off + bx;
    }

    // ---- Loads only: divergent arm split (both arms __ldg) ----
    float2 v0[4], v1[4];
    if (hashed) {
#pragma unroll
        for (int p = 0; p < 4; ++p) {
            const unsigned a = ia[p], bb = ib[p];
            if ((a ^ bb) == 1u) {
                // Pair shares one aligned 16B slot: single LDG.128.
                const unsigned lo = a & ~1u;
                const float2* q = (lo < T) ? (ext + lo) : (ownm + lo);
                const float4 w4 = __ldg((const float4*)q);
                const bool swap = (a & 1u);
                v0[p] = swap ? make_float2(w4.z, w4.w) : make_float2(w4.x, w4.y);
                v1[p] = swap ? make_float2(w4.x, w4.y) : make_float2(w4.z, w4.w);
            } else {
                const float2* qa = (a  < T) ? (ext + a)  : (ownm + a);
                const float2* qb = (bb < T) ? (ext + bb) : (ownm + bb);
                v0[p] = __ldg(qa);
                v1[p] = __ldg(qb);
            }
        }
    } else {
        // Dense levels: all indices inside ext; pairs consecutive (b = a+1),
        // one LDG.128 when a is even.
#pragma unroll
        for (int p = 0; p < 4; ++p) {
            const unsigned a = ia[p];
            if ((a & 1u) == 0u) {
                const float4 w4 = __ldg((const float4*)(ext + a));
                v0[p] = make_float2(w4.x, w4.y);
                v1[p] = make_float2(w4.z, w4.w);
            } else {
                v0[p] = __ldg(ext + a);
                v1[p] = __ldg(ext + a + 1u);
            }
        }
    }

    // Trilinear accumulate (shared).
    const float wx0 = 1.0f - fx, wx1 = fx;
    const float wy[2] = { 1.0f - fy, fy };
    const float wz[2] = { 1.0f - fz, fz };

    float accx = 0.0f, accy = 0.0f;
#pragma unroll
    for (int p = 0; p < 4; ++p) {
        const int cy = p & 1, cz = (p >> 1) & 1;
        const float w = wy[cy] * wz[cz];
        accx += w * (wx0 * v0[p].x + wx1 * v1[p].x);
        accy += w * (wx0 * v0[p].y + wx1 * v1[p].y);
    }

    out[gtid] = make_float2(accx, accy);
}

extern "C" void kernel_launch(void* const* d_in, const int* in_sizes, int n_in,
                              void* d_out, int out_size)
{
    const float*  pts = (const float*)d_in[0];        // [B, 3]
    const float2* ext = (const float2*)d_in[1];       // [524288, 2]
    const float2* own = (const float2*)d_in[2];       // [N_TABLE - 524288, 2]
    float2* out = (float2*)d_out;                     // [B*16] float2

    grid_encode_kernel<<<65536, 256>>>(pts, ext, own, out);
}

// round 16
// speedup vs baseline: 1.0480x; 1.0014x over previous
#include <cuda_runtime.h>
#include <stdint.h>

// B = 1048576, D = 3, L = 16, C = 2, H = 16, S = 1.0
//   res(l) = 16 << l, side = res+1; dense l=0,1,2; hashed l>=3 (hm = 2^19)
//   offsets: 0, 4920, 40864, 315496, then +524288/level (all even)
//   table = concat(ext[524288,2], own[.,2])
//
// R16 = champion structure (R10/R15, 289.1us; ablation-proven over 15
// rounds) + two scheduling-level micros:
//   - 512-thread blocks (grid 32768): fewer CTA transitions, same occupancy
//     bound (32 regs x 2048 thr/SM).
//   - position affine folded to one FMA/axis: pos = px*h + (h+0.5),
//     h = 0.5*scale (trilinear continuity makes the rounding delta O(ulp)).
// Core structure unchanged: thread=(point,level); loads-only arm split;
// per-pair LDG.128 merge when (a^b)==1; threshold ext/own select; all __ldg;
// truncation floor; plain coalesced float2 stores.

#define HASH_SPLIT 524288u
#define P2 2654435761u
#define P3 805459861u

__global__ void __launch_bounds__(512)
grid_encode_kernel(const float* __restrict__ pts,
                   const float2* __restrict__ ext,
                   const float2* __restrict__ own,
                   float2* __restrict__ out)
{
    const unsigned gtid = blockIdx.x * 512u + threadIdx.x;
    const unsigned b = gtid >> 4;
    const unsigned l = gtid & 15u;

    const float px_in = __ldg(&pts[3u * b + 0u]);
    const float py_in = __ldg(&pts[3u * b + 1u]);
    const float pz_in = __ldg(&pts[3u * b + 2u]);

    const unsigned res  = 16u << l;
    const float scale   = (float)(res - 1u);
    const unsigned side = res + 1u;

    // pos = (px+1)*0.5*scale + 0.5 == px*h + (h + 0.5), h = 0.5*scale.
    // pos >= 0.5 always: truncation == floor.
    const float h  = 0.5f * scale;
    const float c0 = h + 0.5f;
    const float posx = fmaf(px_in, h, c0);
    const float posy = fmaf(py_in, h, c0);
    const float posz = fmaf(pz_in, h, c0);

    const unsigned x0 = (unsigned)posx;
    const unsigned y0 = (unsigned)posy;
    const unsigned z0 = (unsigned)posz;
    const float fx = posx - (float)x0;
    const float fy = posy - (float)y0;
    const float fz = posz - (float)z0;

    const bool hashed = (l >= 3u);
    const unsigned off = hashed ? (315496u + (l - 3u) * 524288u)
                                : (l == 0u ? 0u : (l == 1u ? 4920u : 40864u));

    // ext/own threshold: idx < T -> ext + g ; else own + (g - HASH_SPLIT).
    // l<=2: always ext. l==3: straddles. l>=4: always own.
    const unsigned T = (l < 3u) ? 0xFFFFFFFFu : (l == 3u ? HASH_SPLIT : 0u);
    const float2* __restrict__ ownm = own - HASH_SPLIT;

    // Hash per-axis terms (uint32 wraparound; PRIMES = {1, P2, P3})
    const unsigned hy0 = y0 * P2;
    const unsigned hz0 = z0 * P3;
    const unsigned hys[2] = { hy0, hy0 + P2 };
    const unsigned hzs[2] = { hz0, hz0 + P3 };

    // Dense per-axis terms (no modulo: side^3 <= hm for l<=2)
    const unsigned side2 = side * side;
    const unsigned dys[2] = { y0 * side,  y0 * side + side };
    const unsigned dzs[2] = { z0 * side2, z0 * side2 + side2 };

    // Global indices for the 4 (y,z) pairs (shared by both load arms).
    unsigned ia[4], ib[4];
#pragma unroll
    for (int p = 0; p < 4; ++p) {
        const int cy = p & 1, cz = (p >> 1) & 1;
        unsigned a, bx;
        if (hashed) {
            const unsigned hb = hys[cy] ^ hzs[cz];
            a  = (x0 ^ hb) & (HASH_SPLIT - 1u);
            bx = ((x0 + 1u) ^ hb) & (HASH_SPLIT - 1u);
        } else {
            const unsigned db = dys[cy] + dzs[cz];
            a  = x0 + db;
            bx = a + 1u;
        }
        ia[p] = off + a;
        ib[p] = off + bx;
    }

    // ---- Loads only: divergent arm split (both arms __ldg) ----
    float2 v0[4], v1[4];
    if (hashed) {
#pragma unroll
        for (int p = 0; p < 4; ++p) {
            const unsigned a = ia[p], bb = ib[p];
            if ((a ^ bb) == 1u) {
                // Pair shares one aligned 16B slot: single LDG.128.
                const unsigned lo = a & ~1u;
                const float2* q = (lo < T) ? (ext + lo) : (ownm + lo);
                const float4 w4 = __ldg((const float4*)q);
                const bool swap = (a & 1u);
                v0[p] = swap ? make_float2(w4.z, w4.w) : make_float2(w4.x, w4.y);
                v1[p] = swap ? make_float2(w4.x, w4.y) : make_float2(w4.z, w4.w);
            } else {
                const float2* qa = (a  < T) ? (ext + a)  : (ownm + a);
                const float2* qb = (bb < T) ? (ext + bb) : (ownm + bb);
                v0[p] = __ldg(qa);
                v1[p] = __ldg(qb);
            }
        }
    } else {
        // Dense levels: all indices inside ext; pairs consecutive (b = a+1),
        // one LDG.128 when a is even.
#pragma unroll
        for (int p = 0; p < 4; ++p) {
            const unsigned a = ia[p];
            if ((a & 1u) == 0u) {
                const float4 w4 = __ldg((const float4*)(ext + a));
                v0[p] = make_float2(w4.x, w4.y);
                v1[p] = make_float2(w4.z, w4.w);
            } else {
                v0[p] = __ldg(ext + a);
                v1[p] = __ldg(ext + a + 1u);
            }
        }
    }

    // Trilinear accumulate (shared).
    const float wx0 = 1.0f - fx, wx1 = fx;
    const float wy[2] = { 1.0f - fy, fy };
    const float wz[2] = { 1.0f - fz, fz };

    float accx = 0.0f, accy = 0.0f;
#pragma unroll
    for (int p = 0; p < 4; ++p) {
        const int cy = p & 1, cz = (p >> 1) & 1;
        const float w = wy[cy] * wz[cz];
        accx += w * (wx0 * v0[p].x + wx1 * v1[p].x);
        accy += w * (wx0 * v0[p].y + wx1 * v1[p].y);
    }

    out[gtid] = make_float2(accx, accy);
}

extern "C" void kernel_launch(void* const* d_in, const int* in_sizes, int n_in,
                              void* d_out, int out_size)
{
    const float*  pts = (const float*)d_in[0];        // [B, 3]
    const float2* ext = (const float2*)d_in[1];       // [524288, 2]
    const float2* own = (const float2*)d_in[2];       // [N_TABLE - 524288, 2]
    float2* out = (float2*)d_out;                     // [B*16] float2

    // B * L = 16777216 threads; 32768 blocks x 512 threads.
    grid_encode_kernel<<<32768, 512>>>(pts, ext, own, out);
}